// round 6
// baseline (speedup 1.0000x reference)
#include <cuda_runtime.h>
#include <math.h>

// ---------------- problem dims ----------------
#define B     256
#define NIT   50000
#define E     16
#define SL    10
#define HID   512
#define LAT   64
#define RESPD 1024
#define IN_ENC 1200   // SL*E + E + RESP
#define IN_DEC 1104   // LAT + E + RESP
#define KE    160     // SL*E
#define ROWS  2560    // B*SL

#define NCH   50      // item chunks in scoring
#define CHUNK 1000    // items per chunk
#define SUBT  250     // items per shared-memory round
#define LOG2E 1.4426950408889634f

// output layout (float32): z_mean[16384] | z_log_var[16384] | recon_slate[2560] | recon_resp[2560]
#define OUT_ZM 0
#define OUT_LV 16384
#define OUT_SL 32768
#define OUT_RP 35328

// ---------------- device scratch (no allocations allowed) ----------------
__device__ float g_user[B*E];
__device__ float g_x [B*IN_ENC];
__device__ float g_h [B*HID];
__device__ float g_dz[B*IN_DEC];
__device__ float g_dh[B*HID];
__device__ float g_rx[B*KE];
__device__ float g_part[4*B*HID];      // split-K partials (max 4*256*512)
__device__ float g_pmax[NCH*ROWS];
__device__ int   g_pidx[NCH*ROWS];
__device__ float g_psum[NCH*ROWS];

__device__ __forceinline__ float ex2f(float x){
    float y; asm("ex2.approx.f32 %0, %1;" : "=f"(y) : "f"(x)); return y;
}

// ---------------- K1: ragged mean pooling ----------------
// one block per batch row; coalesced user_repr scan, emb gather from L2
__global__ void k_pool(const int* __restrict__ ur, const float* __restrict__ emb){
    int b = blockIdx.x;
    const int* row = ur + (size_t)b * NIT;
    float acc[E];
    #pragma unroll
    for (int e = 0; e < E; e++) acc[e] = 0.f;
    float cnt = 0.f;
    for (int n = threadIdx.x; n < NIT; n += 256){
        if (row[n]){
            cnt += 1.f;
            const float4* e4 = (const float4*)(emb + (size_t)n * E);
            float4 a = e4[0], b2 = e4[1], c = e4[2], d = e4[3];
            acc[0]+=a.x;  acc[1]+=a.y;  acc[2]+=a.z;  acc[3]+=a.w;
            acc[4]+=b2.x; acc[5]+=b2.y; acc[6]+=b2.z; acc[7]+=b2.w;
            acc[8]+=c.x;  acc[9]+=c.y;  acc[10]+=c.z; acc[11]+=c.w;
            acc[12]+=d.x; acc[13]+=d.y; acc[14]+=d.z; acc[15]+=d.w;
        }
    }
    int lane = threadIdx.x & 31, w = threadIdx.x >> 5;
    #pragma unroll
    for (int o = 16; o > 0; o >>= 1){
        #pragma unroll
        for (int e = 0; e < E; e++) acc[e] += __shfl_down_sync(0xffffffffu, acc[e], o);
        cnt += __shfl_down_sync(0xffffffffu, cnt, o);
    }
    __shared__ float sred[8][17];
    if (lane == 0){
        #pragma unroll
        for (int e = 0; e < E; e++) sred[w][e] = acc[e];
        sred[w][16] = cnt;
    }
    __syncthreads();
    if (threadIdx.x < 17){
        float v = 0.f;
        #pragma unroll
        for (int ww = 0; ww < 8; ww++) v += sred[ww][threadIdx.x];
        sred[0][threadIdx.x] = v;
    }
    __syncthreads();
    if (threadIdx.x < 16)
        g_user[b*E + threadIdx.x] = sred[0][threadIdx.x] / sred[0][16];
}

// ---------------- K2: build encoder input x = [slate_emb | user | resp] ----------------
__global__ void k_build_x(const int* __restrict__ slate, const float* __restrict__ resp,
                          const float* __restrict__ emb){
    int b = blockIdx.x, tid = threadIdx.x;
    float* xr = g_x + (size_t)b * IN_ENC;
    if (tid < KE){
        int k = tid >> 4, e = tid & 15;
        xr[tid] = emb[(size_t)slate[b*SL + k] * E + e];
    } else if (tid < KE + E){
        xr[tid] = g_user[b*E + (tid - KE)];
    }
    for (int j = tid; j < RESPD; j += 256)
        xr[KE + E + j] = resp[(size_t)b*RESPD + j];
}

// ---------------- generic split-K fp32 SGEMM: C = A[M,K] @ W[N,K]^T ----------------
#define GBM 64
#define GBN 64
#define GBK 16
#define GPAD 4
__global__ void sgemm_part(const float* __restrict__ A, const float* __restrict__ W,
                           float* __restrict__ Cp, int M, int N, int K, int kslice){
    __shared__ __align__(16) float As[GBK][GBM + GPAD];
    __shared__ __align__(16) float Bs[GBK][GBN + GPAD];
    int tid = threadIdx.x;
    int m0 = blockIdx.x * GBM, n0 = blockIdx.y * GBN;
    int kbeg = blockIdx.z * kslice;
    int kend = min(K, kbeg + kslice);
    int tr = tid >> 4, tc = tid & 15;
    int lr = tid >> 2, lk = (tid & 3) * 4;
    float acc[4][4];
    #pragma unroll
    for (int i = 0; i < 4; i++)
        #pragma unroll
        for (int j = 0; j < 4; j++) acc[i][j] = 0.f;

    for (int k0 = kbeg; k0 < kend; k0 += GBK){
        float4 av = *(const float4*)(A + (size_t)(m0 + lr) * K + k0 + lk);
        float4 bv = make_float4(0.f, 0.f, 0.f, 0.f);
        if (n0 + lr < N) bv = *(const float4*)(W + (size_t)(n0 + lr) * K + k0 + lk);
        __syncthreads();
        As[lk+0][lr] = av.x; As[lk+1][lr] = av.y; As[lk+2][lr] = av.z; As[lk+3][lr] = av.w;
        Bs[lk+0][lr] = bv.x; Bs[lk+1][lr] = bv.y; Bs[lk+2][lr] = bv.z; Bs[lk+3][lr] = bv.w;
        __syncthreads();
        #pragma unroll
        for (int kk = 0; kk < GBK; kk++){
            float4 a4 = *(const float4*)&As[kk][tr*4];
            float4 b4 = *(const float4*)&Bs[kk][tc*4];
            float ra[4] = {a4.x, a4.y, a4.z, a4.w};
            float rb[4] = {b4.x, b4.y, b4.z, b4.w};
            #pragma unroll
            for (int i = 0; i < 4; i++)
                #pragma unroll
                for (int j = 0; j < 4; j++)
                    acc[i][j] += ra[i] * rb[j];
        }
    }
    float* cp = Cp + (size_t)blockIdx.z * M * N;
    #pragma unroll
    for (int i = 0; i < 4; i++){
        int m = m0 + tr*4 + i;
        #pragma unroll
        for (int j = 0; j < 4; j++){
            int n = n0 + tc*4 + j;
            if (n < N) cp[(size_t)m*N + n] = acc[i][j];
        }
    }
}

__global__ void k_reduce(const float* __restrict__ Cp, const float* __restrict__ bias,
                         float* __restrict__ C, int M, int N, int relu){
    int i = blockIdx.x * 256 + threadIdx.x;
    if (i >= M*N) return;
    int n = i % N;
    float v = bias[n];
    #pragma unroll
    for (int z = 0; z < 4; z++) v += Cp[(size_t)z*M*N + i];
    if (relu) v = fmaxf(v, 0.f);
    C[i] = v;
}

// ---------------- K_z: reparameterize + build decoder input ----------------
__global__ void k_z(const float* __restrict__ eps, const float* __restrict__ resp,
                    const float* __restrict__ out){
    int b = blockIdx.x, tid = threadIdx.x;
    float* dzr = g_dz + (size_t)b * IN_DEC;
    if (tid < LAT){
        int idx = b*LAT + tid;
        float mu = out[OUT_ZM + idx];
        float lv = out[OUT_LV + idx];
        dzr[tid] = mu + eps[idx] * expf(0.5f * lv);
    } else if (tid < LAT + E){
        dzr[tid] = g_user[b*E + (tid - LAT)];
    }
    for (int j = tid; j < RESPD; j += 256)
        dzr[LAT + E + j] = resp[(size_t)b*RESPD + j];
}

// ---------------- K_score: fused logits + streaming softmax/argmax partials ----------------
// grid (NCH, ROWS/256). One thread = one (b,k) row. Emb streamed through shared
// in item-pair-packed layout so the dot runs on fma.rn.f32x2 (2 FMA / instr).
// Logits are pre-scaled by log2(e) (rx scaled once) so exp = single MUFU EX2.
// Raw exp2 sums (no max shift): |logit2| is O(10), no overflow possible.
__global__ void k_score(const float* __restrict__ emb){
    __shared__ __align__(16) float sh[SUBT * E];   // [pair][e] as float2 -> 16000 B
    int c = blockIdx.x;
    int r = blockIdx.y * 256 + threadIdx.x;
    int tid = threadIdx.x;

    unsigned long long rx2[E];
    #pragma unroll
    for (int e = 0; e < E; e++){
        unsigned u = __float_as_uint(g_rx[(size_t)r*E + e] * LOG2E);
        rx2[e] = (unsigned long long)u | ((unsigned long long)u << 32);
    }
    float m = -INFINITY, s = 0.f;
    int idx = 0;
    int n0 = c * CHUNK;

    for (int t0 = 0; t0 < CHUNK; t0 += SUBT){
        __syncthreads();
        if (tid < SUBT){
            int n = n0 + t0 + tid;
            const float4* e4 = (const float4*)(emb + (size_t)n * E);
            float* dst = sh + (tid >> 1) * (2*E) + (tid & 1);
            #pragma unroll
            for (int q = 0; q < 4; q++){
                float4 v = e4[q];
                dst[(q*4+0)*2] = v.x; dst[(q*4+1)*2] = v.y;
                dst[(q*4+2)*2] = v.z; dst[(q*4+3)*2] = v.w;
            }
        }
        __syncthreads();
        const ulonglong2* sh128 = (const ulonglong2*)sh;
        #pragma unroll 1
        for (int p = 0; p < SUBT/2; p++){
            unsigned long long a0 = 0ull, a1 = 0ull;
            #pragma unroll
            for (int e2 = 0; e2 < 8; e2++){
                ulonglong2 w = sh128[p*8 + e2];
                asm("fma.rn.f32x2 %0, %1, %2, %0;" : "+l"(a0) : "l"(w.x), "l"(rx2[2*e2]));
                asm("fma.rn.f32x2 %0, %1, %2, %0;" : "+l"(a1) : "l"(w.y), "l"(rx2[2*e2+1]));
            }
            unsigned long long a;
            asm("add.rn.f32x2 %0, %1, %2;" : "=l"(a) : "l"(a0), "l"(a1));
            float l0 = __uint_as_float((unsigned)(a & 0xffffffffull));
            float l1 = __uint_as_float((unsigned)(a >> 32));
            int n = n0 + t0 + 2*p;
            s += ex2f(l0);
            if (l0 > m){ m = l0; idx = n; }
            s += ex2f(l1);
            if (l1 > m){ m = l1; idx = n + 1; }
        }
    }
    g_pmax[c*ROWS + r] = m;
    g_pidx[c*ROWS + r] = idx;
    g_psum[c*ROWS + r] = s;
}

// ---------------- K_final: combine chunk partials, write argmax + resp ----------------
__global__ void k_final(const float* __restrict__ emb, const int* __restrict__ slate,
                        float* __restrict__ out){
    int r = blockIdx.x * 256 + threadIdx.x;  // 0..2559
    float M = -INFINITY, T = 0.f;
    int idx = 0;
    #pragma unroll 1
    for (int c = 0; c < NCH; c++){            // ascending c + strict > => first-occurrence argmax
        float pm = g_pmax[c*ROWS + r];
        if (pm > M){ M = pm; idx = g_pidx[c*ROWS + r]; }
        T += g_psum[c*ROWS + r];
    }
    int ns = slate[r];
    const float* er = emb + (size_t)ns * E;
    const float* rr = g_rx + (size_t)r * E;
    float dot = 0.f;
    #pragma unroll
    for (int e = 0; e < E; e++) dot += rr[e] * er[e];
    out[OUT_SL + r] = (float)idx;
    out[OUT_RP + r] = ex2f(dot * LOG2E) / T;
}

// ---------------- launcher ----------------
extern "C" void kernel_launch(void* const* d_in, const int* in_sizes, int n_in,
                              void* d_out, int out_size){
    const int*   ur    = (const int*)  d_in[0];
    const int*   slate = (const int*)  d_in[1];
    const float* resp  = (const float*)d_in[2];
    const float* eps   = (const float*)d_in[3];
    const float* emb   = (const float*)d_in[4];
    const float* W_enc = (const float*)d_in[5];
    const float* b_enc = (const float*)d_in[6];
    const float* W_mu  = (const float*)d_in[7];
    const float* b_mu  = (const float*)d_in[8];
    const float* W_lv  = (const float*)d_in[9];
    const float* b_lv  = (const float*)d_in[10];
    const float* W_d1  = (const float*)d_in[11];
    const float* b_d1  = (const float*)d_in[12];
    const float* W_d2  = (const float*)d_in[13];
    const float* b_d2  = (const float*)d_in[14];
    float* out = (float*)d_out;

    void *px, *ph, *pdz, *pdh, *prx, *pp;
    cudaGetSymbolAddress(&px,  g_x);
    cudaGetSymbolAddress(&ph,  g_h);
    cudaGetSymbolAddress(&pdz, g_dz);
    cudaGetSymbolAddress(&pdh, g_dh);
    cudaGetSymbolAddress(&prx, g_rx);
    cudaGetSymbolAddress(&pp,  g_part);

    // 1. pooling
    k_pool<<<B, 256>>>(ur, emb);
    // 2. encoder input
    k_build_x<<<B, 256>>>(slate, resp, emb);
    // 3. h = relu(x @ W_enc^T + b_enc)   K=1200 -> kslice=304
    sgemm_part<<<dim3(4,8,4), 256>>>((const float*)px, W_enc, (float*)pp, B, HID, IN_ENC, 304);
    k_reduce<<<(B*HID + 255)/256, 256>>>((const float*)pp, b_enc, (float*)ph, B, HID, 1);
    // 4. z_mean -> out[0:16384]          K=512 -> kslice=128
    sgemm_part<<<dim3(4,1,4), 256>>>((const float*)ph, W_mu, (float*)pp, B, LAT, HID, 128);
    k_reduce<<<(B*LAT + 255)/256, 256>>>((const float*)pp, b_mu, out + OUT_ZM, B, LAT, 0);
    // 5. z_log_var -> out[16384:32768]
    sgemm_part<<<dim3(4,1,4), 256>>>((const float*)ph, W_lv, (float*)pp, B, LAT, HID, 128);
    k_reduce<<<(B*LAT + 255)/256, 256>>>((const float*)pp, b_lv, out + OUT_LV, B, LAT, 0);
    // 6. z = mu + eps*exp(0.5*lv); dz = [z | user | resp]
    k_z<<<B, 256>>>(eps, resp, out);
    // 7. dh = relu(dz @ W_d1^T + b_d1)   K=1104 -> kslice=288
    sgemm_part<<<dim3(4,8,4), 256>>>((const float*)pdz, W_d1, (float*)pp, B, HID, IN_DEC, 288);
    k_reduce<<<(B*HID + 255)/256, 256>>>((const float*)pp, b_d1, (float*)pdh, B, HID, 1);
    // 8. rx = relu(dh @ W_d2^T + b_d2)   N=160, K=512
    sgemm_part<<<dim3(4,3,4), 256>>>((const float*)pdh, W_d2, (float*)pp, B, KE, HID, 128);
    k_reduce<<<(B*KE + 255)/256, 256>>>((const float*)pp, b_d2, (float*)prx, B, KE, 1);
    // 9. fused scoring (logits + softmax partials + argmax partials)
    k_score<<<dim3(NCH, ROWS/256), 256>>>(emb);
    // 10. combine partials, write recon_slate / recon_resp
    k_final<<<ROWS/256, 256>>>(emb, slate, out);
}

// round 7
// speedup vs baseline: 1.0054x; 1.0054x over previous
#include <cuda_runtime.h>
#include <math.h>

// ---------------- problem dims ----------------
#define B     256
#define NIT   50000
#define E     16
#define SL    10
#define HID   512
#define LAT   64
#define RESPD 1024
#define IN_ENC 1200   // SL*E + E + RESP
#define IN_DEC 1104   // LAT + E + RESP
#define KE    160     // SL*E
#define ROWS  2560    // B*SL

#define NCH   50      // item chunks in scoring
#define CHUNK 1000    // items per chunk
#define SUBT  250     // items per shared-memory round
#define LOG2E 1.4426950408889634f

// output layout (float32): z_mean[16384] | z_log_var[16384] | recon_slate[2560] | recon_resp[2560]
#define OUT_ZM 0
#define OUT_LV 16384
#define OUT_SL 32768
#define OUT_RP 35328

// ---------------- device scratch (no allocations allowed) ----------------
__device__ float g_user[B*E];
__device__ float g_x [B*IN_ENC];
__device__ float g_h [B*HID];
__device__ float g_dz[B*IN_DEC];
__device__ float g_dh[B*HID];
__device__ float g_rx[B*KE];
__device__ float g_part[4*B*HID];      // split-K partials (max 4*256*512)
__device__ float g_pmax[NCH*ROWS];
__device__ int   g_pidx[NCH*ROWS];
__device__ float g_psum[NCH*ROWS];

__device__ __forceinline__ float ex2f(float x){
    float y; asm("ex2.approx.f32 %0, %1;" : "=f"(y) : "f"(x)); return y;
}

// ---------------- K1: ragged mean pooling ----------------
// one block per batch row; coalesced user_repr scan, emb gather from L2
__global__ void k_pool(const int* __restrict__ ur, const float* __restrict__ emb){
    int b = blockIdx.x;
    const int* row = ur + (size_t)b * NIT;
    float acc[E];
    #pragma unroll
    for (int e = 0; e < E; e++) acc[e] = 0.f;
    float cnt = 0.f;
    for (int n = threadIdx.x; n < NIT; n += 256){
        if (row[n]){
            cnt += 1.f;
            const float4* e4 = (const float4*)(emb + (size_t)n * E);
            float4 a = e4[0], b2 = e4[1], c = e4[2], d = e4[3];
            acc[0]+=a.x;  acc[1]+=a.y;  acc[2]+=a.z;  acc[3]+=a.w;
            acc[4]+=b2.x; acc[5]+=b2.y; acc[6]+=b2.z; acc[7]+=b2.w;
            acc[8]+=c.x;  acc[9]+=c.y;  acc[10]+=c.z; acc[11]+=c.w;
            acc[12]+=d.x; acc[13]+=d.y; acc[14]+=d.z; acc[15]+=d.w;
        }
    }
    int lane = threadIdx.x & 31, w = threadIdx.x >> 5;
    #pragma unroll
    for (int o = 16; o > 0; o >>= 1){
        #pragma unroll
        for (int e = 0; e < E; e++) acc[e] += __shfl_down_sync(0xffffffffu, acc[e], o);
        cnt += __shfl_down_sync(0xffffffffu, cnt, o);
    }
    __shared__ float sred[8][17];
    if (lane == 0){
        #pragma unroll
        for (int e = 0; e < E; e++) sred[w][e] = acc[e];
        sred[w][16] = cnt;
    }
    __syncthreads();
    if (threadIdx.x < 17){
        float v = 0.f;
        #pragma unroll
        for (int ww = 0; ww < 8; ww++) v += sred[ww][threadIdx.x];
        sred[0][threadIdx.x] = v;
    }
    __syncthreads();
    if (threadIdx.x < 16)
        g_user[b*E + threadIdx.x] = sred[0][threadIdx.x] / sred[0][16];
}

// ---------------- K2: build encoder input x = [slate_emb | user | resp] ----------------
__global__ void k_build_x(const int* __restrict__ slate, const float* __restrict__ resp,
                          const float* __restrict__ emb){
    int b = blockIdx.x, tid = threadIdx.x;
    float* xr = g_x + (size_t)b * IN_ENC;
    if (tid < KE){
        int k = tid >> 4, e = tid & 15;
        xr[tid] = emb[(size_t)slate[b*SL + k] * E + e];
    } else if (tid < KE + E){
        xr[tid] = g_user[b*E + (tid - KE)];
    }
    for (int j = tid; j < RESPD; j += 256)
        xr[KE + E + j] = resp[(size_t)b*RESPD + j];
}

// ---------------- generic split-K fp32 SGEMM: C = A[M,K] @ W[N,K]^T ----------------
#define GBM 64
#define GBN 64
#define GBK 16
#define GPAD 4
__global__ void sgemm_part(const float* __restrict__ A, const float* __restrict__ W,
                           float* __restrict__ Cp, int M, int N, int K, int kslice){
    __shared__ __align__(16) float As[GBK][GBM + GPAD];
    __shared__ __align__(16) float Bs[GBK][GBN + GPAD];
    int tid = threadIdx.x;
    int m0 = blockIdx.x * GBM, n0 = blockIdx.y * GBN;
    int kbeg = blockIdx.z * kslice;
    int kend = min(K, kbeg + kslice);
    int tr = tid >> 4, tc = tid & 15;
    int lr = tid >> 2, lk = (tid & 3) * 4;
    float acc[4][4];
    #pragma unroll
    for (int i = 0; i < 4; i++)
        #pragma unroll
        for (int j = 0; j < 4; j++) acc[i][j] = 0.f;

    for (int k0 = kbeg; k0 < kend; k0 += GBK){
        float4 av = *(const float4*)(A + (size_t)(m0 + lr) * K + k0 + lk);
        float4 bv = make_float4(0.f, 0.f, 0.f, 0.f);
        if (n0 + lr < N) bv = *(const float4*)(W + (size_t)(n0 + lr) * K + k0 + lk);
        __syncthreads();
        As[lk+0][lr] = av.x; As[lk+1][lr] = av.y; As[lk+2][lr] = av.z; As[lk+3][lr] = av.w;
        Bs[lk+0][lr] = bv.x; Bs[lk+1][lr] = bv.y; Bs[lk+2][lr] = bv.z; Bs[lk+3][lr] = bv.w;
        __syncthreads();
        #pragma unroll
        for (int kk = 0; kk < GBK; kk++){
            float4 a4 = *(const float4*)&As[kk][tr*4];
            float4 b4 = *(const float4*)&Bs[kk][tc*4];
            float ra[4] = {a4.x, a4.y, a4.z, a4.w};
            float rb[4] = {b4.x, b4.y, b4.z, b4.w};
            #pragma unroll
            for (int i = 0; i < 4; i++)
                #pragma unroll
                for (int j = 0; j < 4; j++)
                    acc[i][j] += ra[i] * rb[j];
        }
    }
    float* cp = Cp + (size_t)blockIdx.z * M * N;
    #pragma unroll
    for (int i = 0; i < 4; i++){
        int m = m0 + tr*4 + i;
        #pragma unroll
        for (int j = 0; j < 4; j++){
            int n = n0 + tc*4 + j;
            if (n < N) cp[(size_t)m*N + n] = acc[i][j];
        }
    }
}

__global__ void k_reduce(const float* __restrict__ Cp, const float* __restrict__ bias,
                         float* __restrict__ C, int M, int N, int relu){
    int i = blockIdx.x * 256 + threadIdx.x;
    if (i >= M*N) return;
    int n = i % N;
    float v = bias[n];
    #pragma unroll
    for (int z = 0; z < 4; z++) v += Cp[(size_t)z*M*N + i];
    if (relu) v = fmaxf(v, 0.f);
    C[i] = v;
}

// ---------------- K_z: reparameterize + build decoder input ----------------
__global__ void k_z(const float* __restrict__ eps, const float* __restrict__ resp,
                    const float* __restrict__ out){
    int b = blockIdx.x, tid = threadIdx.x;
    float* dzr = g_dz + (size_t)b * IN_DEC;
    if (tid < LAT){
        int idx = b*LAT + tid;
        float mu = out[OUT_ZM + idx];
        float lv = out[OUT_LV + idx];
        dzr[tid] = mu + eps[idx] * expf(0.5f * lv);
    } else if (tid < LAT + E){
        dzr[tid] = g_user[b*E + (tid - LAT)];
    }
    for (int j = tid; j < RESPD; j += 256)
        dzr[LAT + E + j] = resp[(size_t)b*RESPD + j];
}

// ---------------- K_score: fused logits + streaming softmax/argmax partials ----------------
// grid (NCH, ROWS/256). One thread = one (b,k) row. Emb streamed through shared
// in item-pair-packed layout so the dot runs on fma.rn.f32x2 (2 FMA / instr).
// Logits are pre-scaled by log2(e) (rx scaled once) so exp = single MUFU EX2.
// Raw exp2 sums (no max shift): |logit2| is O(10), no overflow possible.
__global__ void k_score(const float* __restrict__ emb){
    __shared__ __align__(16) float sh[SUBT * E];   // [pair][e] as float2 -> 16000 B
    int c = blockIdx.x;
    int r = blockIdx.y * 256 + threadIdx.x;
    int tid = threadIdx.x;

    unsigned long long rx2[E];
    #pragma unroll
    for (int e = 0; e < E; e++){
        unsigned u = __float_as_uint(g_rx[(size_t)r*E + e] * LOG2E);
        rx2[e] = (unsigned long long)u | ((unsigned long long)u << 32);
    }
    float m = -INFINITY, s = 0.f;
    int idx = 0;
    int n0 = c * CHUNK;

    for (int t0 = 0; t0 < CHUNK; t0 += SUBT){
        __syncthreads();
        if (tid < SUBT){
            int n = n0 + t0 + tid;
            const float4* e4 = (const float4*)(emb + (size_t)n * E);
            float* dst = sh + (tid >> 1) * (2*E) + (tid & 1);
            #pragma unroll
            for (int q = 0; q < 4; q++){
                float4 v = e4[q];
                dst[(q*4+0)*2] = v.x; dst[(q*4+1)*2] = v.y;
                dst[(q*4+2)*2] = v.z; dst[(q*4+3)*2] = v.w;
            }
        }
        __syncthreads();
        const ulonglong2* sh128 = (const ulonglong2*)sh;
        #pragma unroll 1
        for (int p = 0; p < SUBT/2; p++){
            unsigned long long a0 = 0ull, a1 = 0ull;
            #pragma unroll
            for (int e2 = 0; e2 < 8; e2++){
                ulonglong2 w = sh128[p*8 + e2];
                asm("fma.rn.f32x2 %0, %1, %2, %0;" : "+l"(a0) : "l"(w.x), "l"(rx2[2*e2]));
                asm("fma.rn.f32x2 %0, %1, %2, %0;" : "+l"(a1) : "l"(w.y), "l"(rx2[2*e2+1]));
            }
            unsigned long long a;
            asm("add.rn.f32x2 %0, %1, %2;" : "=l"(a) : "l"(a0), "l"(a1));
            float l0 = __uint_as_float((unsigned)(a & 0xffffffffull));
            float l1 = __uint_as_float((unsigned)(a >> 32));
            int n = n0 + t0 + 2*p;
            s += ex2f(l0);
            if (l0 > m){ m = l0; idx = n; }
            s += ex2f(l1);
            if (l1 > m){ m = l1; idx = n + 1; }
        }
    }
    g_pmax[c*ROWS + r] = m;
    g_pidx[c*ROWS + r] = idx;
    g_psum[c*ROWS + r] = s;
}

// ---------------- K_final: combine chunk partials, write argmax + resp ----------------
__global__ void k_final(const float* __restrict__ emb, const int* __restrict__ slate,
                        float* __restrict__ out){
    int r = blockIdx.x * 256 + threadIdx.x;  // 0..2559
    float M = -INFINITY, T = 0.f;
    int idx = 0;
    #pragma unroll 1
    for (int c = 0; c < NCH; c++){            // ascending c + strict > => first-occurrence argmax
        float pm = g_pmax[c*ROWS + r];
        if (pm > M){ M = pm; idx = g_pidx[c*ROWS + r]; }
        T += g_psum[c*ROWS + r];
    }
    int ns = slate[r];
    const float* er = emb + (size_t)ns * E;
    const float* rr = g_rx + (size_t)r * E;
    float dot = 0.f;
    #pragma unroll
    for (int e = 0; e < E; e++) dot += rr[e] * er[e];
    out[OUT_SL + r] = (float)idx;
    out[OUT_RP + r] = ex2f(dot * LOG2E) / T;
}

// ---------------- launcher ----------------
extern "C" void kernel_launch(void* const* d_in, const int* in_sizes, int n_in,
                              void* d_out, int out_size){
    const int*   ur    = (const int*)  d_in[0];
    const int*   slate = (const int*)  d_in[1];
    const float* resp  = (const float*)d_in[2];
    const float* eps   = (const float*)d_in[3];
    const float* emb   = (const float*)d_in[4];
    const float* W_enc = (const float*)d_in[5];
    const float* b_enc = (const float*)d_in[6];
    const float* W_mu  = (const float*)d_in[7];
    const float* b_mu  = (const float*)d_in[8];
    const float* W_lv  = (const float*)d_in[9];
    const float* b_lv  = (const float*)d_in[10];
    const float* W_d1  = (const float*)d_in[11];
    const float* b_d1  = (const float*)d_in[12];
    const float* W_d2  = (const float*)d_in[13];
    const float* b_d2  = (const float*)d_in[14];
    float* out = (float*)d_out;

    void *px, *ph, *pdz, *pdh, *prx, *pp;
    cudaGetSymbolAddress(&px,  g_x);
    cudaGetSymbolAddress(&ph,  g_h);
    cudaGetSymbolAddress(&pdz, g_dz);
    cudaGetSymbolAddress(&pdh, g_dh);
    cudaGetSymbolAddress(&prx, g_rx);
    cudaGetSymbolAddress(&pp,  g_part);

    // 1. pooling
    k_pool<<<B, 256>>>(ur, emb);
    // 2. encoder input
    k_build_x<<<B, 256>>>(slate, resp, emb);
    // 3. h = relu(x @ W_enc^T + b_enc)   K=1200 -> kslice=304
    sgemm_part<<<dim3(4,8,4), 256>>>((const float*)px, W_enc, (float*)pp, B, HID, IN_ENC, 304);
    k_reduce<<<(B*HID + 255)/256, 256>>>((const float*)pp, b_enc, (float*)ph, B, HID, 1);
    // 4. z_mean -> out[0:16384]          K=512 -> kslice=128
    sgemm_part<<<dim3(4,1,4), 256>>>((const float*)ph, W_mu, (float*)pp, B, LAT, HID, 128);
    k_reduce<<<(B*LAT + 255)/256, 256>>>((const float*)pp, b_mu, out + OUT_ZM, B, LAT, 0);
    // 5. z_log_var -> out[16384:32768]
    sgemm_part<<<dim3(4,1,4), 256>>>((const float*)ph, W_lv, (float*)pp, B, LAT, HID, 128);
    k_reduce<<<(B*LAT + 255)/256, 256>>>((const float*)pp, b_lv, out + OUT_LV, B, LAT, 0);
    // 6. z = mu + eps*exp(0.5*lv); dz = [z | user | resp]
    k_z<<<B, 256>>>(eps, resp, out);
    // 7. dh = relu(dz @ W_d1^T + b_d1)   K=1104 -> kslice=288
    sgemm_part<<<dim3(4,8,4), 256>>>((const float*)pdz, W_d1, (float*)pp, B, HID, IN_DEC, 288);
    k_reduce<<<(B*HID + 255)/256, 256>>>((const float*)pp, b_d1, (float*)pdh, B, HID, 1);
    // 8. rx = relu(dh @ W_d2^T + b_d2)   N=160, K=512
    sgemm_part<<<dim3(4,3,4), 256>>>((const float*)pdh, W_d2, (float*)pp, B, KE, HID, 128);
    k_reduce<<<(B*KE + 255)/256, 256>>>((const float*)pp, b_d2, (float*)prx, B, KE, 1);
    // 9. fused scoring (logits + softmax partials + argmax partials)
    k_score<<<dim3(NCH, ROWS/256), 256>>>(emb);
    // 10. combine partials, write recon_slate / recon_resp
    k_final<<<ROWS/256, 256>>>(emb, slate, out);
}